// round 13
// baseline (speedup 1.0000x reference)
#include <cuda_runtime.h>
#include <cuda_bf16.h>
#include <stdint.h>
#include <math.h>

#define Hh 224
#define Ww 224
#define NT 49
#define SCALE_Q 0.17677669529663687f
#define LN_EPS 1e-5f
#define NTOKENS (8*224*224)          // 401408

// pre-swizzled bf16 weights (row stride 104, smem-ready)
__device__ __nv_bfloat16 g_wq[288*104];
__device__ __nv_bfloat16 g_wp[96*104];
__device__ __nv_bfloat16 g_w1[384*104];
__device__ __nv_bfloat16 g_w2[4][96*104];            // fc2 K-chunks

// =====================================================================
// helpers
// =====================================================================
__device__ __forceinline__ uint32_t smem_u32(const void* p) {
    uint32_t a;
    asm("{ .reg .u64 t; cvta.to.shared.u64 t, %1; cvt.u32.u64 %0, t; }" : "=r"(a) : "l"(p));
    return a;
}
__device__ __forceinline__ void ldsm4(uint32_t& r0, uint32_t& r1, uint32_t& r2, uint32_t& r3, uint32_t addr) {
    asm volatile("ldmatrix.sync.aligned.m8n8.x4.shared.b16 {%0,%1,%2,%3}, [%4];"
        : "=r"(r0), "=r"(r1), "=r"(r2), "=r"(r3) : "r"(addr));
}
__device__ __forceinline__ void ldsm4t(uint32_t& r0, uint32_t& r1, uint32_t& r2, uint32_t& r3, uint32_t addr) {
    asm volatile("ldmatrix.sync.aligned.m8n8.x4.trans.shared.b16 {%0,%1,%2,%3}, [%4];"
        : "=r"(r0), "=r"(r1), "=r"(r2), "=r"(r3) : "r"(addr));
}
__device__ __forceinline__ void mma16816(float* c, uint32_t a0, uint32_t a1, uint32_t a2, uint32_t a3,
                                         uint32_t b0, uint32_t b1) {
    asm volatile("mma.sync.aligned.m16n8k16.row.col.f32.bf16.bf16.f32 "
        "{%0,%1,%2,%3},{%4,%5,%6,%7},{%8,%9},{%0,%1,%2,%3};"
        : "+f"(c[0]), "+f"(c[1]), "+f"(c[2]), "+f"(c[3])
        : "r"(a0), "r"(a1), "r"(a2), "r"(a3), "r"(b0), "r"(b1));
}
__device__ __forceinline__ uint32_t packbf2(float a, float b) {
    __nv_bfloat162 p = __floats2bfloat162_rn(a, b);
    return *(uint32_t*)&p;
}
// warp GEMM: 16 rows x 32 cols, K=96
template <int SAE, int SBE>
__device__ __forceinline__ void wgemm_16x32(float c[4][4], uint32_t a_base, uint32_t b_base,
                                            int lane, int row0, int ncol0) {
    const int SA = SAE * 2, SB = SBE * 2;
    uint32_t a_addr = a_base + (uint32_t)(row0 + (lane & 7) + ((lane >> 3) & 1) * 8) * SA + (lane >> 4) * 16;
    uint32_t b_addr = b_base + (uint32_t)(ncol0 + (lane & 7) + (lane >> 4) * 8) * SB + ((lane >> 3) & 1) * 16;
    #pragma unroll
    for (int ks = 0; ks < 6; ks++) {
        uint32_t a0, a1, a2, a3;
        ldsm4(a0, a1, a2, a3, a_addr + ks * 32);
        #pragma unroll
        for (int j = 0; j < 2; j++) {
            uint32_t b0, b1, b2, b3;
            ldsm4(b0, b1, b2, b3, b_addr + (uint32_t)j * 16 * SB + ks * 32);
            mma16816(c[2 * j],     a0, a1, a2, a3, b0, b1);
            mma16816(c[2 * j + 1], a0, a1, a2, a3, b2, b3);
        }
    }
}

// =====================================================================
// weight pre-swizzle
// =====================================================================
__global__ __launch_bounds__(256) void prep_weights(
    const float* __restrict__ qkv_w, const float* __restrict__ proj_w,
    const float* __restrict__ fc1_w, const float* __restrict__ fc2_w)
{
    int i = blockIdx.x * 256 + threadIdx.x;
    if (i >= 1152 * 96) return;
    int row = i / 96, col = i % 96;
    float v; __nv_bfloat16* dst;
    if (row < 288)      { v = qkv_w[row * 96 + col];               dst = g_wq + row * 104 + col; }
    else if (row < 384) { int r = row - 288; v = proj_w[r * 96 + col]; dst = g_wp + r * 104 + col; }
    else if (row < 768) { int r = row - 384; v = fc1_w[r * 96 + col];  dst = g_w1 + r * 104 + col; }
    else { int r = row - 768; int kc = r / 96, n = r % 96;
           v = fc2_w[n * 384 + kc * 96 + col]; dst = g_w2[kc] + n * 104 + col; }
    *dst = __float2bfloat16(v);
}

// =====================================================================
// MEGA: full Swin block per 64-token window. 384 threads, 2 CTAs/SM.
// smem overlay (111168B total):
//   As  [0,13312)       : LN1 out -> (phase5+) LN2 out
//   Qs  [13312,51200)   : qkv / o -> dead after proj
//   Hs  [13312,63488)   : fc1+GELU (overlays dead Qs + proj wts head)
//   Wq  [51200,111104)  : qkv wts -> proj wts (base) -> B0/B1 + red
//   B0  [63488,83456) B1 [83456,103424)  red [103424,105472)
//   sregs [111104,111168)
// =====================================================================
__global__ __launch_bounds__(384, 2) void mega_kernel(
    const float* __restrict__ x,
    const float* __restrict__ n1g, const float* __restrict__ n1b,
    const float* __restrict__ qkv_b, const float* __restrict__ proj_b,
    const float* __restrict__ n2g, const float* __restrict__ n2b,
    const float* __restrict__ fc1_b, const float* __restrict__ fc2_b,
    float* __restrict__ out)
{
    extern __shared__ char smraw[];
    __nv_bfloat16* As = (__nv_bfloat16*)smraw;               // 64*104
    __nv_bfloat16* Qs = (__nv_bfloat16*)(smraw + 13312);     // 64*296
    __nv_bfloat16* Hs = (__nv_bfloat16*)(smraw + 13312);     // 64*392 (overlays Qs)
    __nv_bfloat16* Wq = (__nv_bfloat16*)(smraw + 51200);     // 288*104
    __nv_bfloat16* B0 = (__nv_bfloat16*)(smraw + 63488);     // 96*104
    __nv_bfloat16* B1 = (__nv_bfloat16*)(smraw + 83456);     // 96*104
    float* red = (float*)(smraw + 103424);                   // 512 floats
    unsigned char* sregs = (unsigned char*)(smraw + 111104); // 64 bytes
    const int tid = threadIdx.x, lane = tid & 31, wid = tid >> 5;
    const int blk = blockIdx.x;
    const int bI = blk >> 10, wi = (blk >> 5) & 31, wj = blk & 31;
    const int rt = wid & 3, cw = wid >> 2;                   // 4x3 warp grid

    // ---------- phase 1: stage qkv weights + LN1 gather ----------
    {
        const uint4* src = (const uint4*)g_wq;
        uint4* dst = (uint4*)Wq;
        for (int i = tid; i < 3744; i += 384) dst[i] = src[i];
    }
    {
        const float g0 = n1g[lane], g1 = n1g[lane + 32], g2 = n1g[lane + 64];
        const float b0 = n1b[lane], b1 = n1b[lane + 32], b2 = n1b[lane + 64];
        for (int t0 = wid; t0 < 64; t0 += 24) {
            int tt[2] = { t0, t0 + 12 };
            float va_[2][3];
            bool vv[2];
            #pragma unroll
            for (int q = 0; q < 2; q++) {
                int t = tt[q];
                vv[q] = (t < 64) && (t < NT);
                if (t < 64 && lane == 0) sregs[t] = 15;
                if (vv[q]) {
                    int r  = wi * 7 + t / 7;
                    int cl = wj * 7 + t % 7;
                    int rr = (r < 217) ? 0 : ((r < 221) ? 1 : 2);
                    int rc = (cl < 217) ? 0 : ((cl < 221) ? 1 : 2);
                    if (lane == 0) sregs[t] = (unsigned char)(rr * 3 + rc);
                    int sr = r + 3;  if (sr >= Hh) sr -= Hh;
                    int sc = cl + 3; if (sc >= Ww) sc -= Ww;
                    const float* xp = x + ((size_t)(bI * Hh + sr) * Ww + sc) * 96;
                    va_[q][0] = xp[lane]; va_[q][1] = xp[lane + 32]; va_[q][2] = xp[lane + 64];
                }
            }
            #pragma unroll
            for (int q = 0; q < 2; q++) {
                int t = tt[q];
                if (t >= 64) continue;
                __nv_bfloat16* dst = As + t * 104;
                if (vv[q]) {
                    float v0 = va_[q][0], v1 = va_[q][1], v2 = va_[q][2];
                    float s = v0 + v1 + v2;
                    #pragma unroll
                    for (int o = 16; o; o >>= 1) s += __shfl_xor_sync(~0u, s, o);
                    float mu = s * (1.0f / 96.0f);
                    float d0 = v0 - mu, d1 = v1 - mu, d2 = v2 - mu;
                    float vs = d0 * d0 + d1 * d1 + d2 * d2;
                    #pragma unroll
                    for (int o = 16; o; o >>= 1) vs += __shfl_xor_sync(~0u, vs, o);
                    float rs = rsqrtf(vs * (1.0f / 96.0f) + LN_EPS);
                    dst[lane]      = __float2bfloat16(d0 * rs * g0 + b0);
                    dst[lane + 32] = __float2bfloat16(d1 * rs * g1 + b1);
                    dst[lane + 64] = __float2bfloat16(d2 * rs * g2 + b2);
                } else {
                    __nv_bfloat16 z = __float2bfloat16(0.f);
                    dst[lane] = z; dst[lane + 32] = z; dst[lane + 64] = z;
                }
            }
        }
    }
    __syncthreads();

    const uint32_t a_base = smem_u32(As), q_base = smem_u32(Qs), w_base = smem_u32(Wq);
    const uint32_t h_base = smem_u32(Hs);
    uint32_t bbase[2] = { smem_u32(B0), smem_u32(B1) };
    uint4* bdst[2] = { (uint4*)B0, (uint4*)B1 };

    // ---------- phase 2: qkv, 3 chunks back-to-back, no barriers ----------
    #pragma unroll
    for (int ch = 0; ch < 3; ch++) {
        float c[4][4];
        #pragma unroll
        for (int j = 0; j < 4; j++) { c[j][0]=0.f; c[j][1]=0.f; c[j][2]=0.f; c[j][3]=0.f; }
        wgemm_16x32<104, 104>(c, a_base, w_base + (uint32_t)ch * 19968, lane, rt * 16, cw * 32);
        const float qs = (ch == 0) ? SCALE_Q : 1.0f;
        int row0 = rt * 16 + (lane >> 2);
        #pragma unroll
        for (int j = 0; j < 4; j++) {
            int jc = ch * 96 + cw * 32 + j * 8 + (lane & 3) * 2;
            float bi0 = __ldg(qkv_b + jc), bi1 = __ldg(qkv_b + jc + 1);
            *(uint32_t*)(Qs + row0 * 296 + jc)       = packbf2((c[j][0] + bi0) * qs, (c[j][1] + bi1) * qs);
            *(uint32_t*)(Qs + (row0 + 8) * 296 + jc) = packbf2((c[j][2] + bi0) * qs, (c[j][3] + bi1) * qs);
        }
    }
    __syncthreads();

    // prefetch proj weights into Wq base (during attention)
    {
        const uint4* src = (const uint4*)g_wp;
        uint4* dst = (uint4*)Wq;
        for (int i = tid; i < 1248; i += 384) dst[i] = src[i];
    }

    // ---------- phase 3: attention, 1 task per warp ----------
    {
        const int h = cw;
        float c[8][4];
        #pragma unroll
        for (int j = 0; j < 8; j++) { c[j][0]=0.f; c[j][1]=0.f; c[j][2]=0.f; c[j][3]=0.f; }
        uint32_t a_addr = q_base + (uint32_t)(rt * 16 + (lane & 7) + ((lane >> 3) & 1) * 8) * 592 + h * 64 + (lane >> 4) * 16;
        uint32_t b_addr = q_base + (uint32_t)((lane & 7) + (lane >> 4) * 8) * 592 + 192 + h * 64 + ((lane >> 3) & 1) * 16;
        #pragma unroll
        for (int ks = 0; ks < 2; ks++) {
            uint32_t a0, a1, a2, a3;
            ldsm4(a0, a1, a2, a3, a_addr + ks * 32);
            #pragma unroll
            for (int j2 = 0; j2 < 4; j2++) {
                uint32_t b0, b1, b2, b3;
                ldsm4(b0, b1, b2, b3, b_addr + (uint32_t)j2 * 16 * 592 + ks * 32);
                mma16816(c[2 * j2],     a0, a1, a2, a3, b0, b1);
                mma16816(c[2 * j2 + 1], a0, a1, a2, a3, b2, b3);
            }
        }
        int t1 = rt * 16 + (lane >> 2), t2 = t1 + 8;
        int reg1 = sregs[t1], reg2 = sregs[t2];
        float mx1 = -1e30f, mx2 = -1e30f;
        #pragma unroll
        for (int j = 0; j < 8; j++) {
            #pragma unroll
            for (int e = 0; e < 2; e++) {
                int u = j * 8 + (lane & 3) * 2 + e;
                int ru = sregs[u];
                c[j][e]     += (ru == reg1) ? 0.f : -100.f;
                c[j][2 + e] += (ru == reg2) ? 0.f : -100.f;
                mx1 = fmaxf(mx1, c[j][e]);
                mx2 = fmaxf(mx2, c[j][2 + e]);
            }
        }
        mx1 = fmaxf(mx1, __shfl_xor_sync(~0u, mx1, 1)); mx1 = fmaxf(mx1, __shfl_xor_sync(~0u, mx1, 2));
        mx2 = fmaxf(mx2, __shfl_xor_sync(~0u, mx2, 1)); mx2 = fmaxf(mx2, __shfl_xor_sync(~0u, mx2, 2));
        float s1 = 0.f, s2 = 0.f;
        #pragma unroll
        for (int j = 0; j < 8; j++) {
            c[j][0] = __expf(c[j][0] - mx1); c[j][1] = __expf(c[j][1] - mx1);
            c[j][2] = __expf(c[j][2] - mx2); c[j][3] = __expf(c[j][3] - mx2);
            s1 += c[j][0] + c[j][1]; s2 += c[j][2] + c[j][3];
        }
        s1 += __shfl_xor_sync(~0u, s1, 1); s1 += __shfl_xor_sync(~0u, s1, 2);
        s2 += __shfl_xor_sync(~0u, s2, 1); s2 += __shfl_xor_sync(~0u, s2, 2);
        float i1 = 1.0f / (s1 + 1e-20f), i2 = 1.0f / (s2 + 1e-20f);
        uint32_t ap[4][4];
        #pragma unroll
        for (int s = 0; s < 4; s++) {
            ap[s][0] = packbf2(c[2*s][0]   * i1, c[2*s][1]   * i1);
            ap[s][1] = packbf2(c[2*s][2]   * i2, c[2*s][3]   * i2);
            ap[s][2] = packbf2(c[2*s+1][0] * i1, c[2*s+1][1] * i1);
            ap[s][3] = packbf2(c[2*s+1][2] * i2, c[2*s+1][3] * i2);
        }
        float c2[4][4];
        #pragma unroll
        for (int n = 0; n < 4; n++) { c2[n][0]=0.f; c2[n][1]=0.f; c2[n][2]=0.f; c2[n][3]=0.f; }
        uint32_t vb = q_base + (uint32_t)((lane & 7) + ((lane >> 3) & 1) * 8) * 592 + 384 + h * 64 + (lane >> 4) * 16;
        #pragma unroll
        for (int ks = 0; ks < 4; ks++) {
            uint32_t b0, b1, b2, b3;
            ldsm4t(b0, b1, b2, b3, vb + (uint32_t)ks * 16 * 592);
            mma16816(c2[0], ap[ks][0], ap[ks][1], ap[ks][2], ap[ks][3], b0, b1);
            mma16816(c2[1], ap[ks][0], ap[ks][1], ap[ks][2], ap[ks][3], b2, b3);
            ldsm4t(b0, b1, b2, b3, vb + (uint32_t)ks * 16 * 592 + 32);
            mma16816(c2[2], ap[ks][0], ap[ks][1], ap[ks][2], ap[ks][3], b0, b1);
            mma16816(c2[3], ap[ks][0], ap[ks][1], ap[ks][2], ap[ks][3], b2, b3);
        }
        int row = rt * 16 + (lane >> 2);
        #pragma unroll
        for (int n = 0; n < 4; n++) {
            int col = h * 32 + n * 8 + (lane & 3) * 2;
            *(uint32_t*)(Qs + row * 296 + col)       = packbf2(c2[n][0], c2[n][1]);
            *(uint32_t*)(Qs + (row + 8) * 296 + col) = packbf2(c2[n][2], c2[n][3]);
        }
    }
    __syncthreads();

    // ---------- phase 4: proj + bias + residual; res stays in registers ----------
    float res[4][4];
    #pragma unroll
    for (int j = 0; j < 4; j++) { res[j][0]=0.f; res[j][1]=0.f; res[j][2]=0.f; res[j][3]=0.f; }
    wgemm_16x32<296, 104>(res, q_base, w_base, lane, rt * 16, cw * 32);

    const int r1 = rt * 16 + (lane >> 2), r2 = r1 + 8;
    const bool va = r1 < NT, vb2 = r2 < NT;
    size_t nt1 = 0, nt2 = 0;
    {
        int tl = va ? r1 : 0;
        int r = wi * 7 + tl / 7, cl = wj * 7 + tl % 7;
        int sr = r + 3;  if (sr >= Hh) sr -= Hh;
        int sc = cl + 3; if (sc >= Ww) sc -= Ww;
        nt1 = ((size_t)(bI * Hh + sr)) * Ww + sc;
        tl = vb2 ? r2 : 0;
        r = wi * 7 + tl / 7; cl = wj * 7 + tl % 7;
        sr = r + 3;  if (sr >= Hh) sr -= Hh;
        sc = cl + 3; if (sc >= Ww) sc -= Ww;
        nt2 = ((size_t)(bI * Hh + sr)) * Ww + sc;
    }
    {
        float s1a = 0.f, s2a = 0.f, s1b = 0.f, s2b = 0.f;
        #pragma unroll
        for (int j = 0; j < 4; j++) {
            int col = cw * 32 + j * 8 + (lane & 3) * 2;
            float bi0 = __ldg(proj_b + col), bi1 = __ldg(proj_b + col + 1);
            float2 xa = va  ? *(const float2*)(x + nt1 * 96 + col) : make_float2(0.f, 0.f);
            float2 xb = vb2 ? *(const float2*)(x + nt2 * 96 + col) : make_float2(0.f, 0.f);
            res[j][0] += bi0 + xa.x; res[j][1] += bi1 + xa.y;
            res[j][2] += bi0 + xb.x; res[j][3] += bi1 + xb.y;
            s1a += res[j][0] + res[j][1]; s2a += res[j][0]*res[j][0] + res[j][1]*res[j][1];
            s1b += res[j][2] + res[j][3]; s2b += res[j][2]*res[j][2] + res[j][3]*res[j][3];
        }
        s1a += __shfl_xor_sync(~0u, s1a, 1); s1a += __shfl_xor_sync(~0u, s1a, 2);
        s2a += __shfl_xor_sync(~0u, s2a, 1); s2a += __shfl_xor_sync(~0u, s2a, 2);
        s1b += __shfl_xor_sync(~0u, s1b, 1); s1b += __shfl_xor_sync(~0u, s1b, 2);
        s2b += __shfl_xor_sync(~0u, s2b, 1); s2b += __shfl_xor_sync(~0u, s2b, 2);
        if ((lane & 3) == 0) {
            red[r1 * 4 + cw] = s1a; red[256 + r1 * 4 + cw] = s2a;
            red[r2 * 4 + cw] = s1b; red[256 + r2 * 4 + cw] = s2b;
        }
    }
    __syncthreads();

    // ---------- phase 5: LN2 -> As (smem), stage fc1 chunk0 -> B0 ----------
    {
        float mu1 = (red[r1 * 4] + red[r1 * 4 + 1] + red[r1 * 4 + 2]) * (1.f / 96.f);
        float mu2 = (red[r2 * 4] + red[r2 * 4 + 1] + red[r2 * 4 + 2]) * (1.f / 96.f);
        float rs1 = rsqrtf((red[256 + r1 * 4] + red[256 + r1 * 4 + 1] + red[256 + r1 * 4 + 2]) * (1.f / 96.f) - mu1 * mu1 + LN_EPS);
        float rs2 = rsqrtf((red[256 + r2 * 4] + red[256 + r2 * 4 + 1] + red[256 + r2 * 4 + 2]) * (1.f / 96.f) - mu2 * mu2 + LN_EPS);
        #pragma unroll
        for (int j = 0; j < 4; j++) {
            int col = cw * 32 + j * 8 + (lane & 3) * 2;
            float gg0 = __ldg(n2g + col), gg1 = __ldg(n2g + col + 1);
            float nb0 = __ldg(n2b + col), nb1 = __ldg(n2b + col + 1);
            if (va)
                *(uint32_t*)(As + r1 * 104 + col) =
                    packbf2((res[j][0] - mu1) * rs1 * gg0 + nb0, (res[j][1] - mu1) * rs1 * gg1 + nb1);
            if (vb2)
                *(uint32_t*)(As + r2 * 104 + col) =
                    packbf2((res[j][2] - mu2) * rs2 * gg0 + nb0, (res[j][3] - mu2) * rs2 * gg1 + nb1);
        }
        const uint4* src = (const uint4*)g_w1;
        for (int i = tid; i < 1248; i += 384) bdst[0][i] = src[i];
    }
    __syncthreads();

    // ---------- phase 6: fc1 + GELU -> Hs, double-buffered weights ----------
    for (int ch = 0; ch < 4; ch++) {
        {
            const uint4* src = (ch < 3) ? (const uint4*)(g_w1 + (ch + 1) * 96 * 104)
                                        : (const uint4*)(g_w2[0]);
            uint4* d = bdst[(ch + 1) & 1];
            for (int i = tid; i < 1248; i += 384) d[i] = src[i];
        }
        float cf[4][4];
        #pragma unroll
        for (int j = 0; j < 4; j++) { cf[j][0]=0.f; cf[j][1]=0.f; cf[j][2]=0.f; cf[j][3]=0.f; }
        wgemm_16x32<104, 104>(cf, a_base, bbase[ch & 1], lane, rt * 16, cw * 32);
        #pragma unroll
        for (int j = 0; j < 4; j++) {
            int col = ch * 96 + cw * 32 + j * 8 + (lane & 3) * 2;
            float bi0 = __ldg(fc1_b + col), bi1 = __ldg(fc1_b + col + 1);
            float v0 = cf[j][0] + bi0, v1 = cf[j][1] + bi1;
            float v2 = cf[j][2] + bi0, v3 = cf[j][3] + bi1;
            v0 = 0.5f * v0 * (1.0f + erff(v0 * 0.70710678118654752f));
            v1 = 0.5f * v1 * (1.0f + erff(v1 * 0.70710678118654752f));
            v2 = 0.5f * v2 * (1.0f + erff(v2 * 0.70710678118654752f));
            v3 = 0.5f * v3 * (1.0f + erff(v3 * 0.70710678118654752f));
            *(uint32_t*)(Hs + r1 * 392 + col) = packbf2(v0, v1);
            *(uint32_t*)(Hs + r2 * 392 + col) = packbf2(v2, v3);
        }
        __syncthreads();
    }

    // ---------- phase 7: fc2, accumulate over 4 K-chunks from Hs ----------
    float c2[4][4];
    #pragma unroll
    for (int j = 0; j < 4; j++) { c2[j][0]=0.f; c2[j][1]=0.f; c2[j][2]=0.f; c2[j][3]=0.f; }
    for (int kc = 0; kc < 4; kc++) {
        if (kc < 3) {
            const uint4* src = (const uint4*)(g_w2[kc + 1]);
            uint4* d = bdst[(kc + 1) & 1];
            for (int i = tid; i < 1248; i += 384) d[i] = src[i];
        }
        wgemm_16x32<392, 104>(c2, h_base + kc * 192, bbase[kc & 1], lane, rt * 16, cw * 32);
        if (kc < 3) __syncthreads();
    }

    // ---------- phase 8: out = c2 + bias + res ----------
    #pragma unroll
    for (int j = 0; j < 4; j++) {
        int col = cw * 32 + j * 8 + (lane & 3) * 2;
        float bi0 = __ldg(fc2_b + col), bi1 = __ldg(fc2_b + col + 1);
        if (va)
            *(float2*)(out + nt1 * 96 + col) =
                make_float2(c2[j][0] + bi0 + res[j][0], c2[j][1] + bi1 + res[j][1]);
        if (vb2)
            *(float2*)(out + nt2 * 96 + col) =
                make_float2(c2[j][2] + bi0 + res[j][2], c2[j][3] + bi1 + res[j][3]);
    }
}

// =====================================================================
extern "C" void kernel_launch(void* const* d_in, const int* in_sizes, int n_in,
                              void* d_out, int out_size)
{
    (void)in_sizes; (void)n_in; (void)out_size;
    const float* x      = (const float*)d_in[0];
    const float* n1g    = (const float*)d_in[2];
    const float* n1b    = (const float*)d_in[3];
    const float* qkv_w  = (const float*)d_in[4];
    const float* qkv_b  = (const float*)d_in[5];
    const float* proj_w = (const float*)d_in[6];
    const float* proj_b = (const float*)d_in[7];
    const float* n2g    = (const float*)d_in[8];
    const float* n2b    = (const float*)d_in[9];
    const float* fc1_w  = (const float*)d_in[10];
    const float* fc1_b  = (const float*)d_in[11];
    const float* fc2_w  = (const float*)d_in[12];
    const float* fc2_b  = (const float*)d_in[13];
    float* out = (float*)d_out;

    const int smMega = 111168;
    cudaFuncSetAttribute(mega_kernel, cudaFuncAttributeMaxDynamicSharedMemorySize, smMega);

    prep_weights<<<432, 256>>>(qkv_w, proj_w, fc1_w, fc2_w);
    mega_kernel<<<8192, 384, smMega>>>(x, n1g, n1b, qkv_b, proj_b, n2g, n2b,
                                       fc1_b, fc2_b, out);
}

// round 15
// speedup vs baseline: 1.2139x; 1.2139x over previous
#include <cuda_runtime.h>
#include <cuda_bf16.h>
#include <stdint.h>
#include <math.h>

#define Hh 224
#define Ww 224
#define NT 49
#define SCALE_Q 0.17677669529663687f
#define LN_EPS 1e-5f
#define NTOKENS (8*224*224)          // 401408

// fp32/bf16 activation scratch
__device__ float         g_x1[(size_t)NTOKENS*96];   // x + attn residual (natural)
__device__ __nv_bfloat16 g_x2[(size_t)NTOKENS*96];   // LN2 out (natural)

// pre-swizzled bf16 weights (row stride 104, smem-ready)
__device__ __nv_bfloat16 g_wq[288*104];
__device__ __nv_bfloat16 g_wp[96*104];
__device__ __nv_bfloat16 g_w1[384*104];
__device__ __nv_bfloat16 g_w2[4][96*104];            // fc2 K-chunks

// =====================================================================
// helpers
// =====================================================================
__device__ __forceinline__ uint32_t smem_u32(const void* p) {
    uint32_t a;
    asm("{ .reg .u64 t; cvta.to.shared.u64 t, %1; cvt.u32.u64 %0, t; }" : "=r"(a) : "l"(p));
    return a;
}
__device__ __forceinline__ void cpa16(uint32_t d, const void* s) {
    asm volatile("cp.async.cg.shared.global [%0], [%1], 16;" :: "r"(d), "l"(s));
}
#define CPA_COMMIT() asm volatile("cp.async.commit_group;" ::: "memory")
#define CPA_WAIT0()  asm volatile("cp.async.wait_group 0;" ::: "memory")
__device__ __forceinline__ void ldsm4(uint32_t& r0, uint32_t& r1, uint32_t& r2, uint32_t& r3, uint32_t addr) {
    asm volatile("ldmatrix.sync.aligned.m8n8.x4.shared.b16 {%0,%1,%2,%3}, [%4];"
        : "=r"(r0), "=r"(r1), "=r"(r2), "=r"(r3) : "r"(addr));
}
__device__ __forceinline__ void ldsm4t(uint32_t& r0, uint32_t& r1, uint32_t& r2, uint32_t& r3, uint32_t addr) {
    asm volatile("ldmatrix.sync.aligned.m8n8.x4.trans.shared.b16 {%0,%1,%2,%3}, [%4];"
        : "=r"(r0), "=r"(r1), "=r"(r2), "=r"(r3) : "r"(addr));
}
__device__ __forceinline__ void mma16816(float* c, uint32_t a0, uint32_t a1, uint32_t a2, uint32_t a3,
                                         uint32_t b0, uint32_t b1) {
    asm volatile("mma.sync.aligned.m16n8k16.row.col.f32.bf16.bf16.f32 "
        "{%0,%1,%2,%3},{%4,%5,%6,%7},{%8,%9},{%0,%1,%2,%3};"
        : "+f"(c[0]), "+f"(c[1]), "+f"(c[2]), "+f"(c[3])
        : "r"(a0), "r"(a1), "r"(a2), "r"(a3), "r"(b0), "r"(b1));
}
__device__ __forceinline__ uint32_t packbf2(float a, float b) {
    __nv_bfloat162 p = __floats2bfloat162_rn(a, b);
    return *(uint32_t*)&p;
}
// warp GEMM: 16 rows x 32 cols, K=96
template <int SAE, int SBE>
__device__ __forceinline__ void wgemm_16x32(float c[4][4], uint32_t a_base, uint32_t b_base,
                                            int lane, int row0, int ncol0) {
    const int SA = SAE * 2, SB = SBE * 2;
    uint32_t a_addr = a_base + (uint32_t)(row0 + (lane & 7) + ((lane >> 3) & 1) * 8) * SA + (lane >> 4) * 16;
    uint32_t b_addr = b_base + (uint32_t)(ncol0 + (lane & 7) + (lane >> 4) * 8) * SB + ((lane >> 3) & 1) * 16;
    #pragma unroll
    for (int ks = 0; ks < 6; ks++) {
        uint32_t a0, a1, a2, a3;
        ldsm4(a0, a1, a2, a3, a_addr + ks * 32);
        #pragma unroll
        for (int j = 0; j < 2; j++) {
            uint32_t b0, b1, b2, b3;
            ldsm4(b0, b1, b2, b3, b_addr + (uint32_t)j * 16 * SB + ks * 32);
            mma16816(c[2 * j],     a0, a1, a2, a3, b0, b1);
            mma16816(c[2 * j + 1], a0, a1, a2, a3, b2, b3);
        }
    }
}

// =====================================================================
// weight pre-swizzle
// =====================================================================
__global__ __launch_bounds__(256) void prep_weights(
    const float* __restrict__ qkv_w, const float* __restrict__ proj_w,
    const float* __restrict__ fc1_w, const float* __restrict__ fc2_w)
{
    int i = blockIdx.x * 256 + threadIdx.x;
    if (i >= 1152 * 96) return;
    int row = i / 96, col = i % 96;
    float v; __nv_bfloat16* dst;
    if (row < 288)      { v = qkv_w[row * 96 + col];               dst = g_wq + row * 104 + col; }
    else if (row < 384) { int r = row - 288; v = proj_w[r * 96 + col]; dst = g_wp + r * 104 + col; }
    else if (row < 768) { int r = row - 384; v = fc1_w[r * 96 + col];  dst = g_w1 + r * 104 + col; }
    else { int r = row - 768; int kc = r / 96, n = r % 96;
           v = fc2_w[n * 384 + kc * 96 + col]; dst = g_w2[kc] + n * 104 + col; }
    *dst = __float2bfloat16(v);
}

// =====================================================================
// ATTN: 1 window / block, 384 threads (12 warps), 2 CTAs/SM
// Full qkv weight resident in smem, staged via cp.async during LN1;
// 3 qkv chunks back-to-back, no barriers.
// =====================================================================
__global__ __launch_bounds__(384, 2) void attn_kernel(
    const float* __restrict__ x,
    const float* __restrict__ n1g, const float* __restrict__ n1b,
    const float* __restrict__ qkv_b, const float* __restrict__ proj_b,
    const float* __restrict__ n2g, const float* __restrict__ n2b)
{
    extern __shared__ char smraw[];
    __nv_bfloat16* As = (__nv_bfloat16*)smraw;              // 64*104
    __nv_bfloat16* Qs = (__nv_bfloat16*)(smraw + 13312);    // 64*296
    __nv_bfloat16* Wq = (__nv_bfloat16*)(smraw + 51200);    // 288*104 (qkv; later proj)
    unsigned char* sregs = (unsigned char*)(smraw + 111104);// 64 region bytes
    const int tid = threadIdx.x, lane = tid & 31, wid = tid >> 5;
    const int blk = blockIdx.x;
    const int bI = blk >> 10, wi = (blk >> 5) & 31, wj = blk & 31;
    const int rt = wid & 3, cw = wid >> 2;                   // 4x3 warp grid
    const uint32_t w_base = smem_u32(Wq);

    // ---------- stage FULL qkv weight via cp.async (overlaps LN1) ----------
    {
        const uint4* src = (const uint4*)g_wq;
        for (int i = tid; i < 3744; i += 384) cpa16(w_base + i * 16, src + i);
        CPA_COMMIT();
    }

    // ---------- LN1 + shifted gather + region bytes ----------
    {
        const float g0 = n1g[lane], g1 = n1g[lane + 32], g2 = n1g[lane + 64];
        const float b0 = n1b[lane], b1 = n1b[lane + 32], b2 = n1b[lane + 64];
        for (int t0 = wid; t0 < 64; t0 += 24) {
            int tt[2] = { t0, t0 + 12 };
            float va_[2][3];
            bool vv[2];
            #pragma unroll
            for (int q = 0; q < 2; q++) {
                int t = tt[q];
                vv[q] = (t < 64) && (t < NT);
                if (t < 64 && lane == 0) sregs[t] = 15;
                if (vv[q]) {
                    int r  = wi * 7 + t / 7;
                    int cl = wj * 7 + t % 7;
                    int rr = (r < 217) ? 0 : ((r < 221) ? 1 : 2);
                    int rc = (cl < 217) ? 0 : ((cl < 221) ? 1 : 2);
                    if (lane == 0) sregs[t] = (unsigned char)(rr * 3 + rc);
                    int sr = r + 3;  if (sr >= Hh) sr -= Hh;
                    int sc = cl + 3; if (sc >= Ww) sc -= Ww;
                    const float* xp = x + ((size_t)(bI * Hh + sr) * Ww + sc) * 96;
                    va_[q][0] = xp[lane]; va_[q][1] = xp[lane + 32]; va_[q][2] = xp[lane + 64];
                }
            }
            #pragma unroll
            for (int q = 0; q < 2; q++) {
                int t = tt[q];
                if (t >= 64) continue;
                __nv_bfloat16* dst = As + t * 104;
                if (vv[q]) {
                    float v0 = va_[q][0], v1 = va_[q][1], v2 = va_[q][2];
                    float s = v0 + v1 + v2;
                    #pragma unroll
                    for (int o = 16; o; o >>= 1) s += __shfl_xor_sync(~0u, s, o);
                    float mu = s * (1.0f / 96.0f);
                    float d0 = v0 - mu, d1 = v1 - mu, d2 = v2 - mu;
                    float vs = d0 * d0 + d1 * d1 + d2 * d2;
                    #pragma unroll
                    for (int o = 16; o; o >>= 1) vs += __shfl_xor_sync(~0u, vs, o);
                    float rs = rsqrtf(vs * (1.0f / 96.0f) + LN_EPS);
                    dst[lane]      = __float2bfloat16(d0 * rs * g0 + b0);
                    dst[lane + 32] = __float2bfloat16(d1 * rs * g1 + b1);
                    dst[lane + 64] = __float2bfloat16(d2 * rs * g2 + b2);
                } else {
                    __nv_bfloat16 z = __float2bfloat16(0.f);
                    dst[lane] = z; dst[lane + 32] = z; dst[lane + 64] = z;
                }
            }
        }
    }
    CPA_WAIT0();
    __syncthreads();

    const uint32_t a_base = smem_u32(As), q_base = smem_u32(Qs);

    // ---------- qkv: 3 chunks back-to-back, NO barriers (Wq resident) ----------
    #pragma unroll
    for (int ch = 0; ch < 3; ch++) {
        float c[4][4];
        #pragma unroll
        for (int j = 0; j < 4; j++) { c[j][0]=0.f; c[j][1]=0.f; c[j][2]=0.f; c[j][3]=0.f; }
        wgemm_16x32<104, 104>(c, a_base, w_base + (uint32_t)ch * 19968, lane, rt * 16, cw * 32);
        const float qs = (ch == 0) ? SCALE_Q : 1.0f;
        int row0 = rt * 16 + (lane >> 2);
        #pragma unroll
        for (int j = 0; j < 4; j++) {
            int jc = ch * 96 + cw * 32 + j * 8 + (lane & 3) * 2;
            float bi0 = __ldg(qkv_b + jc), bi1 = __ldg(qkv_b + jc + 1);
            *(uint32_t*)(Qs + row0 * 296 + jc)       = packbf2((c[j][0] + bi0) * qs, (c[j][1] + bi1) * qs);
            *(uint32_t*)(Qs + (row0 + 8) * 296 + jc) = packbf2((c[j][2] + bi0) * qs, (c[j][3] + bi1) * qs);
        }
    }
    __syncthreads();

    // prefetch proj weights into (now dead) Wq base via cp.async (during attention)
    {
        const uint4* src = (const uint4*)g_wp;
        for (int i = tid; i < 1248; i += 384) cpa16(w_base + i * 16, src + i);
        CPA_COMMIT();
    }

    // ---------- attention: 1 task per warp (h=cw, rowtile=rt) ----------
    {
        const int h = cw;
        float c[8][4];
        #pragma unroll
        for (int j = 0; j < 8; j++) { c[j][0]=0.f; c[j][1]=0.f; c[j][2]=0.f; c[j][3]=0.f; }
        uint32_t a_addr = q_base + (uint32_t)(rt * 16 + (lane & 7) + ((lane >> 3) & 1) * 8) * 592 + h * 64 + (lane >> 4) * 16;
        uint32_t b_addr = q_base + (uint32_t)((lane & 7) + (lane >> 4) * 8) * 592 + 192 + h * 64 + ((lane >> 3) & 1) * 16;
        #pragma unroll
        for (int ks = 0; ks < 2; ks++) {
            uint32_t a0, a1, a2, a3;
            ldsm4(a0, a1, a2, a3, a_addr + ks * 32);
            #pragma unroll
            for (int j2 = 0; j2 < 4; j2++) {
                uint32_t b0, b1, b2, b3;
                ldsm4(b0, b1, b2, b3, b_addr + (uint32_t)j2 * 16 * 592 + ks * 32);
                mma16816(c[2 * j2],     a0, a1, a2, a3, b0, b1);
                mma16816(c[2 * j2 + 1], a0, a1, a2, a3, b2, b3);
            }
        }
        int t1 = rt * 16 + (lane >> 2), t2 = t1 + 8;
        int reg1 = sregs[t1], reg2 = sregs[t2];
        float mx1 = -1e30f, mx2 = -1e30f;
        #pragma unroll
        for (int j = 0; j < 8; j++) {
            #pragma unroll
            for (int e = 0; e < 2; e++) {
                int u = j * 8 + (lane & 3) * 2 + e;
                int ru = sregs[u];
                c[j][e]     += (ru == reg1) ? 0.f : -100.f;
                c[j][2 + e] += (ru == reg2) ? 0.f : -100.f;
                mx1 = fmaxf(mx1, c[j][e]);
                mx2 = fmaxf(mx2, c[j][2 + e]);
            }
        }
        mx1 = fmaxf(mx1, __shfl_xor_sync(~0u, mx1, 1)); mx1 = fmaxf(mx1, __shfl_xor_sync(~0u, mx1, 2));
        mx2 = fmaxf(mx2, __shfl_xor_sync(~0u, mx2, 1)); mx2 = fmaxf(mx2, __shfl_xor_sync(~0u, mx2, 2));
        float s1 = 0.f, s2 = 0.f;
        #pragma unroll
        for (int j = 0; j < 8; j++) {
            c[j][0] = __expf(c[j][0] - mx1); c[j][1] = __expf(c[j][1] - mx1);
            c[j][2] = __expf(c[j][2] - mx2); c[j][3] = __expf(c[j][3] - mx2);
            s1 += c[j][0] + c[j][1]; s2 += c[j][2] + c[j][3];
        }
        s1 += __shfl_xor_sync(~0u, s1, 1); s1 += __shfl_xor_sync(~0u, s1, 2);
        s2 += __shfl_xor_sync(~0u, s2, 1); s2 += __shfl_xor_sync(~0u, s2, 2);
        float i1 = 1.0f / (s1 + 1e-20f), i2 = 1.0f / (s2 + 1e-20f);
        uint32_t ap[4][4];
        #pragma unroll
        for (int s = 0; s < 4; s++) {
            ap[s][0] = packbf2(c[2*s][0]   * i1, c[2*s][1]   * i1);
            ap[s][1] = packbf2(c[2*s][2]   * i2, c[2*s][3]   * i2);
            ap[s][2] = packbf2(c[2*s+1][0] * i1, c[2*s+1][1] * i1);
            ap[s][3] = packbf2(c[2*s+1][2] * i2, c[2*s+1][3] * i2);
        }
        float c2[4][4];
        #pragma unroll
        for (int n = 0; n < 4; n++) { c2[n][0]=0.f; c2[n][1]=0.f; c2[n][2]=0.f; c2[n][3]=0.f; }
        uint32_t vb = q_base + (uint32_t)((lane & 7) + ((lane >> 3) & 1) * 8) * 592 + 384 + h * 64 + (lane >> 4) * 16;
        #pragma unroll
        for (int ks = 0; ks < 4; ks++) {
            uint32_t b0, b1, b2, b3;
            ldsm4t(b0, b1, b2, b3, vb + (uint32_t)ks * 16 * 592);
            mma16816(c2[0], ap[ks][0], ap[ks][1], ap[ks][2], ap[ks][3], b0, b1);
            mma16816(c2[1], ap[ks][0], ap[ks][1], ap[ks][2], ap[ks][3], b2, b3);
            ldsm4t(b0, b1, b2, b3, vb + (uint32_t)ks * 16 * 592 + 32);
            mma16816(c2[2], ap[ks][0], ap[ks][1], ap[ks][2], ap[ks][3], b0, b1);
            mma16816(c2[3], ap[ks][0], ap[ks][1], ap[ks][2], ap[ks][3], b2, b3);
        }
        int row = rt * 16 + (lane >> 2);
        #pragma unroll
        for (int n = 0; n < 4; n++) {
            int col = h * 32 + n * 8 + (lane & 3) * 2;
            *(uint32_t*)(Qs + row * 296 + col)       = packbf2(c2[n][0], c2[n][1]);
            *(uint32_t*)(Qs + (row + 8) * 296 + col) = packbf2(c2[n][2], c2[n][3]);
        }
    }
    CPA_WAIT0();
    __syncthreads();

    // ---------- proj (+bias +residual +fused LN2) ----------
    float c[4][4];
    #pragma unroll
    for (int j = 0; j < 4; j++) { c[j][0]=0.f; c[j][1]=0.f; c[j][2]=0.f; c[j][3]=0.f; }
    wgemm_16x32<296, 104>(c, q_base, w_base, lane, rt * 16, cw * 32);

    int r1 = rt * 16 + (lane >> 2), r2 = r1 + 8;
    bool va = r1 < NT, vb2 = r2 < NT;
    size_t nt1 = 0, nt2 = 0;
    {
        int tl = va ? r1 : 0;
        int r = wi * 7 + tl / 7, cl = wj * 7 + tl % 7;
        int sr = r + 3;  if (sr >= Hh) sr -= Hh;
        int sc = cl + 3; if (sc >= Ww) sc -= Ww;
        nt1 = ((size_t)(bI * Hh + sr)) * Ww + sc;
        tl = vb2 ? r2 : 0;
        r = wi * 7 + tl / 7; cl = wj * 7 + tl % 7;
        sr = r + 3;  if (sr >= Hh) sr -= Hh;
        sc = cl + 3; if (sc >= Ww) sc -= Ww;
        nt2 = ((size_t)(bI * Hh + sr)) * Ww + sc;
    }
    float s1a = 0.f, s2a = 0.f, s1b = 0.f, s2b = 0.f;
    #pragma unroll
    for (int j = 0; j < 4; j++) {
        int col = cw * 32 + j * 8 + (lane & 3) * 2;
        float bi0 = __ldg(proj_b + col), bi1 = __ldg(proj_b + col + 1);
        float2 xa = va  ? *(const float2*)(x + nt1 * 96 + col) : make_float2(0.f, 0.f);
        float2 xb = vb2 ? *(const float2*)(x + nt2 * 96 + col) : make_float2(0.f, 0.f);
        float o0 = c[j][0] + bi0 + xa.x, o1 = c[j][1] + bi1 + xa.y;
        float o2 = c[j][2] + bi0 + xb.x, o3 = c[j][3] + bi1 + xb.y;
        c[j][0] = o0; c[j][1] = o1; c[j][2] = o2; c[j][3] = o3;
        if (va)  *(float2*)(g_x1 + nt1 * 96 + col) = make_float2(o0, o1);
        if (vb2) *(float2*)(g_x1 + nt2 * 96 + col) = make_float2(o2, o3);
        s1a += o0 + o1; s2a += o0 * o0 + o1 * o1;
        s1b += o2 + o3; s2b += o2 * o2 + o3 * o3;
    }
    s1a += __shfl_xor_sync(~0u, s1a, 1); s1a += __shfl_xor_sync(~0u, s1a, 2);
    s2a += __shfl_xor_sync(~0u, s2a, 1); s2a += __shfl_xor_sync(~0u, s2a, 2);
    s1b += __shfl_xor_sync(~0u, s1b, 1); s1b += __shfl_xor_sync(~0u, s1b, 2);
    s2b += __shfl_xor_sync(~0u, s2b, 1); s2b += __shfl_xor_sync(~0u, s2b, 2);
    float* red = (float*)As;
    if ((lane & 3) == 0) {
        red[r1 * 4 + cw] = s1a; red[256 + r1 * 4 + cw] = s2a;
        red[r2 * 4 + cw] = s1b; red[256 + r2 * 4 + cw] = s2b;
    }
    __syncthreads();
    float mu1 = (red[r1 * 4] + red[r1 * 4 + 1] + red[r1 * 4 + 2]) * (1.f / 96.f);
    float mu2 = (red[r2 * 4] + red[r2 * 4 + 1] + red[r2 * 4 + 2]) * (1.f / 96.f);
    float rs1 = rsqrtf((red[256 + r1 * 4] + red[256 + r1 * 4 + 1] + red[256 + r1 * 4 + 2]) * (1.f / 96.f) - mu1 * mu1 + LN_EPS);
    float rs2 = rsqrtf((red[256 + r2 * 4] + red[256 + r2 * 4 + 1] + red[256 + r2 * 4 + 2]) * (1.f / 96.f) - mu2 * mu2 + LN_EPS);
    #pragma unroll
    for (int j = 0; j < 4; j++) {
        int col = cw * 32 + j * 8 + (lane & 3) * 2;
        float gg0 = __ldg(n2g + col), gg1 = __ldg(n2g + col + 1);
        float nb0 = __ldg(n2b + col), nb1 = __ldg(n2b + col + 1);
        if (va)
            *(uint32_t*)(g_x2 + nt1 * 96 + col) =
                packbf2((c[j][0] - mu1) * rs1 * gg0 + nb0, (c[j][1] - mu1) * rs1 * gg1 + nb1);
        if (vb2)
            *(uint32_t*)(g_x2 + nt2 * 96 + col) =
                packbf2((c[j][2] - mu2) * rs2 * gg0 + nb0, (c[j][3] - mu2) * rs2 * gg1 + nb1);
    }
}

// =====================================================================
// MLP merged: 64-row tile, 384 threads (4x3 warp grid), H in smem,
// cp.async double-buffered weight staging
// =====================================================================
__global__ __launch_bounds__(384, 2) void mlp_kernel(
    const float* __restrict__ fc1_b, const float* __restrict__ fc2_b,
    float* __restrict__ out)
{
    extern __shared__ char smraw[];
    __nv_bfloat16* As = (__nv_bfloat16*)smraw;               // 64*104
    __nv_bfloat16* Hs = (__nv_bfloat16*)(smraw + 13312);     // 64*392
    const int tid = threadIdx.x, lane = tid & 31, wid = tid >> 5;
    const int rt = wid & 3, cw = wid >> 2;
    const uint32_t a_base = smem_u32(As), h_base = smem_u32(Hs);
    const uint32_t b_sm[2] = { (uint32_t)(63488), (uint32_t)(83456) };
    uint32_t bbase[2] = { smem_u32(smraw + 63488), smem_u32(smraw + 83456) };
    (void)b_sm;

    // stage A tile + fc1 chunk0 via cp.async
    {
        const __nv_bfloat16* a0 = g_x2 + (size_t)blockIdx.x * 64 * 96;
        for (int i = tid; i < 64 * 12; i += 384) {
            int r = i / 12, c8 = i % 12;
            cpa16(a_base + (uint32_t)(r * 104 + c8 * 8) * 2, a0 + (size_t)r * 96 + c8 * 8);
        }
        const uint4* src = (const uint4*)g_w1;
        for (int i = tid; i < 1248; i += 384) cpa16(bbase[0] + i * 16, src + i);
        CPA_COMMIT();
    }
    CPA_WAIT0();
    __syncthreads();

    // ---------- fc1 + GELU -> Hs, cp.async-pipelined weight staging ----------
    for (int ch = 0; ch < 4; ch++) {
        {
            const uint4* src = (ch < 3) ? (const uint4*)(g_w1 + (ch + 1) * 96 * 104)
                                        : (const uint4*)(g_w2[0]);
            uint32_t d = bbase[(ch + 1) & 1];
            for (int i = tid; i < 1248; i += 384) cpa16(d + i * 16, src + i);
            CPA_COMMIT();
        }
        float c[4][4];
        #pragma unroll
        for (int j = 0; j < 4; j++) { c[j][0]=0.f; c[j][1]=0.f; c[j][2]=0.f; c[j][3]=0.f; }
        wgemm_16x32<104, 104>(c, a_base, bbase[ch & 1], lane, rt * 16, cw * 32);
        int row0 = rt * 16 + (lane >> 2);
        #pragma unroll
        for (int j = 0; j < 4; j++) {
            int col = ch * 96 + cw * 32 + j * 8 + (lane & 3) * 2;
            float bi0 = __ldg(fc1_b + col), bi1 = __ldg(fc1_b + col + 1);
            float v0 = c[j][0] + bi0, v1 = c[j][1] + bi1;
            float v2 = c[j][2] + bi0, v3 = c[j][3] + bi1;
            v0 = 0.5f * v0 * (1.0f + erff(v0 * 0.70710678118654752f));
            v1 = 0.5f * v1 * (1.0f + erff(v1 * 0.70710678118654752f));
            v2 = 0.5f * v2 * (1.0f + erff(v2 * 0.70710678118654752f));
            v3 = 0.5f * v3 * (1.0f + erff(v3 * 0.70710678118654752f));
            *(uint32_t*)(Hs + row0 * 392 + col)       = packbf2(v0, v1);
            *(uint32_t*)(Hs + (row0 + 8) * 392 + col) = packbf2(v2, v3);
        }
        CPA_WAIT0();
        __syncthreads();
    }

    // ---------- fc2: accumulate over 4 K-chunks from Hs ----------
    float c2[4][4];
    #pragma unroll
    for (int j = 0; j < 4; j++) { c2[j][0]=0.f; c2[j][1]=0.f; c2[j][2]=0.f; c2[j][3]=0.f; }
    for (int kc = 0; kc < 4; kc++) {
        if (kc < 3) {
            const uint4* src = (const uint4*)(g_w2[kc + 1]);
            uint32_t d = bbase[(kc + 1) & 1];
            for (int i = tid; i < 1248; i += 384) cpa16(d + i * 16, src + i);
            CPA_COMMIT();
        }
        wgemm_16x32<392, 104>(c2, h_base + kc * 192, bbase[kc & 1], lane, rt * 16, cw * 32);
        if (kc < 3) { CPA_WAIT0(); __syncthreads(); }
    }

    // ---------- bias + residual -> out ----------
    const size_t row0 = (size_t)blockIdx.x * 64 + rt * 16 + (lane >> 2);
    #pragma unroll
    for (int j = 0; j < 4; j++) {
        int col = cw * 32 + j * 8 + (lane & 3) * 2;
        float bi0 = __ldg(fc2_b + col), bi1 = __ldg(fc2_b + col + 1);
        float2 r0 = *(const float2*)(g_x1 + row0 * 96 + col);
        float2 r1 = *(const float2*)(g_x1 + (row0 + 8) * 96 + col);
        *(float2*)(out + row0 * 96 + col)       = make_float2(c2[j][0] + bi0 + r0.x, c2[j][1] + bi1 + r0.y);
        *(float2*)(out + (row0 + 8) * 96 + col) = make_float2(c2[j][2] + bi0 + r1.x, c2[j][3] + bi1 + r1.y);
    }
}

// =====================================================================
extern "C" void kernel_launch(void* const* d_in, const int* in_sizes, int n_in,
                              void* d_out, int out_size)
{
    (void)in_sizes; (void)n_in; (void)out_size;
    const float* x      = (const float*)d_in[0];
    const float* n1g    = (const float*)d_in[2];
    const float* n1b    = (const float*)d_in[3];
    const float* qkv_w  = (const float*)d_in[4];
    const float* qkv_b  = (const float*)d_in[5];
    const float* proj_w = (const float*)d_in[6];
    const float* proj_b = (const float*)d_in[7];
    const float* n2g    = (const float*)d_in[8];
    const float* n2b    = (const float*)d_in[9];
    const float* fc1_w  = (const float*)d_in[10];
    const float* fc1_b  = (const float*)d_in[11];
    const float* fc2_w  = (const float*)d_in[12];
    const float* fc2_b  = (const float*)d_in[13];
    float* out = (float*)d_out;

    const int smAttn = 111168;
    const int smMlp  = 103424;

    cudaFuncSetAttribute(attn_kernel, cudaFuncAttributeMaxDynamicSharedMemorySize, smAttn);
    cudaFuncSetAttribute(mlp_kernel,  cudaFuncAttributeMaxDynamicSharedMemorySize, smMlp);

    prep_weights<<<432, 256>>>(qkv_w, proj_w, fc1_w, fc2_w);
    attn_kernel<<<8192, 384, smAttn>>>(x, n1g, n1b, qkv_b, proj_b, n2g, n2b);
    mlp_kernel<<<NTOKENS/64, 384, smMlp>>>(fc1_b, fc2_b, out);
}

// round 16
// speedup vs baseline: 1.2416x; 1.0228x over previous
#include <cuda_runtime.h>
#include <cuda_bf16.h>
#include <stdint.h>
#include <math.h>

#define Hh 224
#define Ww 224
#define NT 49
#define SCALE_Q 0.17677669529663687f
#define LN_EPS 1e-5f
#define NTOKENS (8*224*224)          // 401408

// fp32/bf16 activation scratch
__device__ float         g_x1[(size_t)NTOKENS*96];   // x + attn residual (natural)
__device__ __nv_bfloat16 g_x2[(size_t)NTOKENS*96];   // LN2 out (natural)

// pre-swizzled bf16 weights (row stride 104, smem-ready)
__device__ __nv_bfloat16 g_wq[288*104];
__device__ __nv_bfloat16 g_wp[96*104];
__device__ __nv_bfloat16 g_w1[384*104];
__device__ __nv_bfloat16 g_w2[4][96*104];            // fc2 K-chunks

// =====================================================================
// helpers
// =====================================================================
__device__ __forceinline__ uint32_t smem_u32(const void* p) {
    uint32_t a;
    asm("{ .reg .u64 t; cvta.to.shared.u64 t, %1; cvt.u32.u64 %0, t; }" : "=r"(a) : "l"(p));
    return a;
}
__device__ __forceinline__ void cpa16(uint32_t d, const void* s) {
    asm volatile("cp.async.cg.shared.global [%0], [%1], 16;" :: "r"(d), "l"(s));
}
#define CPA_COMMIT() asm volatile("cp.async.commit_group;" ::: "memory")
#define CPA_WAIT0()  asm volatile("cp.async.wait_group 0;" ::: "memory")
__device__ __forceinline__ void ldsm4(uint32_t& r0, uint32_t& r1, uint32_t& r2, uint32_t& r3, uint32_t addr) {
    asm volatile("ldmatrix.sync.aligned.m8n8.x4.shared.b16 {%0,%1,%2,%3}, [%4];"
        : "=r"(r0), "=r"(r1), "=r"(r2), "=r"(r3) : "r"(addr));
}
__device__ __forceinline__ void ldsm4t(uint32_t& r0, uint32_t& r1, uint32_t& r2, uint32_t& r3, uint32_t addr) {
    asm volatile("ldmatrix.sync.aligned.m8n8.x4.trans.shared.b16 {%0,%1,%2,%3}, [%4];"
        : "=r"(r0), "=r"(r1), "=r"(r2), "=r"(r3) : "r"(addr));
}
__device__ __forceinline__ void mma16816(float* c, uint32_t a0, uint32_t a1, uint32_t a2, uint32_t a3,
                                         uint32_t b0, uint32_t b1) {
    asm volatile("mma.sync.aligned.m16n8k16.row.col.f32.bf16.bf16.f32 "
        "{%0,%1,%2,%3},{%4,%5,%6,%7},{%8,%9},{%0,%1,%2,%3};"
        : "+f"(c[0]), "+f"(c[1]), "+f"(c[2]), "+f"(c[3])
        : "r"(a0), "r"(a1), "r"(a2), "r"(a3), "r"(b0), "r"(b1));
}
__device__ __forceinline__ uint32_t packbf2(float a, float b) {
    __nv_bfloat162 p = __floats2bfloat162_rn(a, b);
    return *(uint32_t*)&p;
}
// warp GEMM: 16 rows x 32 cols, K=96
template <int SAE, int SBE>
__device__ __forceinline__ void wgemm_16x32(float c[4][4], uint32_t a_base, uint32_t b_base,
                                            int lane, int row0, int ncol0) {
    const int SA = SAE * 2, SB = SBE * 2;
    uint32_t a_addr = a_base + (uint32_t)(row0 + (lane & 7) + ((lane >> 3) & 1) * 8) * SA + (lane >> 4) * 16;
    uint32_t b_addr = b_base + (uint32_t)(ncol0 + (lane & 7) + (lane >> 4) * 8) * SB + ((lane >> 3) & 1) * 16;
    #pragma unroll
    for (int ks = 0; ks < 6; ks++) {
        uint32_t a0, a1, a2, a3;
        ldsm4(a0, a1, a2, a3, a_addr + ks * 32);
        #pragma unroll
        for (int j = 0; j < 2; j++) {
            uint32_t b0, b1, b2, b3;
            ldsm4(b0, b1, b2, b3, b_addr + (uint32_t)j * 16 * SB + ks * 32);
            mma16816(c[2 * j],     a0, a1, a2, a3, b0, b1);
            mma16816(c[2 * j + 1], a0, a1, a2, a3, b2, b3);
        }
    }
}

// =====================================================================
// weight pre-swizzle
// =====================================================================
__global__ __launch_bounds__(256) void prep_weights(
    const float* __restrict__ qkv_w, const float* __restrict__ proj_w,
    const float* __restrict__ fc1_w, const float* __restrict__ fc2_w)
{
    int i = blockIdx.x * 256 + threadIdx.x;
    if (i >= 1152 * 96) return;
    int row = i / 96, col = i % 96;
    float v; __nv_bfloat16* dst;
    if (row < 288)      { v = qkv_w[row * 96 + col];               dst = g_wq + row * 104 + col; }
    else if (row < 384) { int r = row - 288; v = proj_w[r * 96 + col]; dst = g_wp + r * 104 + col; }
    else if (row < 768) { int r = row - 384; v = fc1_w[r * 96 + col];  dst = g_w1 + r * 104 + col; }
    else { int r = row - 768; int kc = r / 96, n = r % 96;
           v = fc2_w[n * 384 + kc * 96 + col]; dst = g_w2[kc] + n * 104 + col; }
    *dst = __float2bfloat16(v);
}

// =====================================================================
// ATTN: 1 window / block, 384 threads (12 warps), 2 CTAs/SM.
// cp.async stages BOTH qkv weights and the x-tile (into dead Qs region);
// LN1 reads x from smem. 3 qkv chunks back-to-back, no barriers.
// =====================================================================
__global__ __launch_bounds__(384, 2) void attn_kernel(
    const float* __restrict__ x,
    const float* __restrict__ n1g, const float* __restrict__ n1b,
    const float* __restrict__ qkv_b, const float* __restrict__ proj_b,
    const float* __restrict__ n2g, const float* __restrict__ n2b)
{
    extern __shared__ char smraw[];
    __nv_bfloat16* As = (__nv_bfloat16*)smraw;              // 64*104
    __nv_bfloat16* Qs = (__nv_bfloat16*)(smraw + 13312);    // 64*296 (first: fp32 x-stage)
    float*         xs = (float*)(smraw + 13312);            // 49*96 fp32 staging (overlay)
    __nv_bfloat16* Wq = (__nv_bfloat16*)(smraw + 51200);    // 288*104 (qkv; later proj)
    unsigned char* sregs = (unsigned char*)(smraw + 111104);// 64 region bytes
    const int tid = threadIdx.x, lane = tid & 31, wid = tid >> 5;
    const int blk = blockIdx.x;
    const int bI = blk >> 10, wi = (blk >> 5) & 31, wj = blk & 31;
    const int rt = wid & 3, cw = wid >> 2;                   // 4x3 warp grid
    const uint32_t w_base = smem_u32(Wq);
    const uint32_t xs_base = smem_u32(xs);

    // ---------- stage qkv weights + x window tile via cp.async ----------
    {
        const uint4* src = (const uint4*)g_wq;
        for (int i = tid; i < 3744; i += 384) cpa16(w_base + i * 16, src + i);
    }
    for (int i = tid; i < NT * 24; i += 384) {
        int t = i / 24, c = i % 24;
        int r  = wi * 7 + t / 7;
        int cl = wj * 7 + t % 7;
        int sr = r + 3;  if (sr >= Hh) sr -= Hh;
        int sc = cl + 3; if (sc >= Ww) sc -= Ww;
        const float* xp = x + ((size_t)(bI * Hh + sr) * Ww + sc) * 96;
        cpa16(xs_base + (uint32_t)(t * 96 + c * 4) * 4, xp + c * 4);
    }
    CPA_COMMIT();
    // region bytes (cheap ALU, no loads)
    if (tid < 64) {
        unsigned char v = 15;
        if (tid < NT) {
            int r  = wi * 7 + tid / 7;
            int cl = wj * 7 + tid % 7;
            int rr = (r < 217) ? 0 : ((r < 221) ? 1 : 2);
            int rc = (cl < 217) ? 0 : ((cl < 221) ? 1 : 2);
            v = (unsigned char)(rr * 3 + rc);
        }
        sregs[tid] = v;
    }
    CPA_WAIT0();
    __syncthreads();

    // ---------- LN1 from smem -> As ----------
    {
        const float g0 = n1g[lane], g1 = n1g[lane + 32], g2 = n1g[lane + 64];
        const float b0 = n1b[lane], b1 = n1b[lane + 32], b2 = n1b[lane + 64];
        for (int t = wid; t < 64; t += 12) {
            __nv_bfloat16* dst = As + t * 104;
            if (t < NT) {
                const float* xp = xs + t * 96;
                float v0 = xp[lane], v1 = xp[lane + 32], v2 = xp[lane + 64];
                float s = v0 + v1 + v2;
                #pragma unroll
                for (int o = 16; o; o >>= 1) s += __shfl_xor_sync(~0u, s, o);
                float mu = s * (1.0f / 96.0f);
                float d0 = v0 - mu, d1 = v1 - mu, d2 = v2 - mu;
                float vs = d0 * d0 + d1 * d1 + d2 * d2;
                #pragma unroll
                for (int o = 16; o; o >>= 1) vs += __shfl_xor_sync(~0u, vs, o);
                float rs = rsqrtf(vs * (1.0f / 96.0f) + LN_EPS);
                dst[lane]      = __float2bfloat16(d0 * rs * g0 + b0);
                dst[lane + 32] = __float2bfloat16(d1 * rs * g1 + b1);
                dst[lane + 64] = __float2bfloat16(d2 * rs * g2 + b2);
            } else {
                __nv_bfloat16 z = __float2bfloat16(0.f);
                dst[lane] = z; dst[lane + 32] = z; dst[lane + 64] = z;
            }
        }
    }
    __syncthreads();

    const uint32_t a_base = smem_u32(As), q_base = smem_u32(Qs);

    // ---------- qkv: 3 chunks back-to-back, NO barriers (Wq resident) ----------
    #pragma unroll
    for (int ch = 0; ch < 3; ch++) {
        float c[4][4];
        #pragma unroll
        for (int j = 0; j < 4; j++) { c[j][0]=0.f; c[j][1]=0.f; c[j][2]=0.f; c[j][3]=0.f; }
        wgemm_16x32<104, 104>(c, a_base, w_base + (uint32_t)ch * 19968, lane, rt * 16, cw * 32);
        const float qs = (ch == 0) ? SCALE_Q : 1.0f;
        int row0 = rt * 16 + (lane >> 2);
        #pragma unroll
        for (int j = 0; j < 4; j++) {
            int jc = ch * 96 + cw * 32 + j * 8 + (lane & 3) * 2;
            float bi0 = __ldg(qkv_b + jc), bi1 = __ldg(qkv_b + jc + 1);
            *(uint32_t*)(Qs + row0 * 296 + jc)       = packbf2((c[j][0] + bi0) * qs, (c[j][1] + bi1) * qs);
            *(uint32_t*)(Qs + (row0 + 8) * 296 + jc) = packbf2((c[j][2] + bi0) * qs, (c[j][3] + bi1) * qs);
        }
    }
    __syncthreads();

    // prefetch proj weights into (now dead) Wq base via cp.async (during attention)
    {
        const uint4* src = (const uint4*)g_wp;
        for (int i = tid; i < 1248; i += 384) cpa16(w_base + i * 16, src + i);
        CPA_COMMIT();
    }

    // ---------- attention: 1 task per warp (h=cw, rowtile=rt) ----------
    {
        const int h = cw;
        float c[8][4];
        #pragma unroll
        for (int j = 0; j < 8; j++) { c[j][0]=0.f; c[j][1]=0.f; c[j][2]=0.f; c[j][3]=0.f; }
        uint32_t a_addr = q_base + (uint32_t)(rt * 16 + (lane & 7) + ((lane >> 3) & 1) * 8) * 592 + h * 64 + (lane >> 4) * 16;
        uint32_t b_addr = q_base + (uint32_t)((lane & 7) + (lane >> 4) * 8) * 592 + 192 + h * 64 + ((lane >> 3) & 1) * 16;
        #pragma unroll
        for (int ks = 0; ks < 2; ks++) {
            uint32_t a0, a1, a2, a3;
            ldsm4(a0, a1, a2, a3, a_addr + ks * 32);
            #pragma unroll
            for (int j2 = 0; j2 < 4; j2++) {
                uint32_t b0, b1, b2, b3;
                ldsm4(b0, b1, b2, b3, b_addr + (uint32_t)j2 * 16 * 592 + ks * 32);
                mma16816(c[2 * j2],     a0, a1, a2, a3, b0, b1);
                mma16816(c[2 * j2 + 1], a0, a1, a2, a3, b2, b3);
            }
        }
        int t1 = rt * 16 + (lane >> 2), t2 = t1 + 8;
        int reg1 = sregs[t1], reg2 = sregs[t2];
        float mx1 = -1e30f, mx2 = -1e30f;
        #pragma unroll
        for (int j = 0; j < 8; j++) {
            #pragma unroll
            for (int e = 0; e < 2; e++) {
                int u = j * 8 + (lane & 3) * 2 + e;
                int ru = sregs[u];
                c[j][e]     += (ru == reg1) ? 0.f : -100.f;
                c[j][2 + e] += (ru == reg2) ? 0.f : -100.f;
                mx1 = fmaxf(mx1, c[j][e]);
                mx2 = fmaxf(mx2, c[j][2 + e]);
            }
        }
        mx1 = fmaxf(mx1, __shfl_xor_sync(~0u, mx1, 1)); mx1 = fmaxf(mx1, __shfl_xor_sync(~0u, mx1, 2));
        mx2 = fmaxf(mx2, __shfl_xor_sync(~0u, mx2, 1)); mx2 = fmaxf(mx2, __shfl_xor_sync(~0u, mx2, 2));
        float s1 = 0.f, s2 = 0.f;
        #pragma unroll
        for (int j = 0; j < 8; j++) {
            c[j][0] = __expf(c[j][0] - mx1); c[j][1] = __expf(c[j][1] - mx1);
            c[j][2] = __expf(c[j][2] - mx2); c[j][3] = __expf(c[j][3] - mx2);
            s1 += c[j][0] + c[j][1]; s2 += c[j][2] + c[j][3];
        }
        s1 += __shfl_xor_sync(~0u, s1, 1); s1 += __shfl_xor_sync(~0u, s1, 2);
        s2 += __shfl_xor_sync(~0u, s2, 1); s2 += __shfl_xor_sync(~0u, s2, 2);
        float i1 = 1.0f / (s1 + 1e-20f), i2 = 1.0f / (s2 + 1e-20f);
        uint32_t ap[4][4];
        #pragma unroll
        for (int s = 0; s < 4; s++) {
            ap[s][0] = packbf2(c[2*s][0]   * i1, c[2*s][1]   * i1);
            ap[s][1] = packbf2(c[2*s][2]   * i2, c[2*s][3]   * i2);
            ap[s][2] = packbf2(c[2*s+1][0] * i1, c[2*s+1][1] * i1);
            ap[s][3] = packbf2(c[2*s+1][2] * i2, c[2*s+1][3] * i2);
        }
        float c2[4][4];
        #pragma unroll
        for (int n = 0; n < 4; n++) { c2[n][0]=0.f; c2[n][1]=0.f; c2[n][2]=0.f; c2[n][3]=0.f; }
        uint32_t vb = q_base + (uint32_t)((lane & 7) + ((lane >> 3) & 1) * 8) * 592 + 384 + h * 64 + (lane >> 4) * 16;
        #pragma unroll
        for (int ks = 0; ks < 4; ks++) {
            uint32_t b0, b1, b2, b3;
            ldsm4t(b0, b1, b2, b3, vb + (uint32_t)ks * 16 * 592);
            mma16816(c2[0], ap[ks][0], ap[ks][1], ap[ks][2], ap[ks][3], b0, b1);
            mma16816(c2[1], ap[ks][0], ap[ks][1], ap[ks][2], ap[ks][3], b2, b3);
            ldsm4t(b0, b1, b2, b3, vb + (uint32_t)ks * 16 * 592 + 32);
            mma16816(c2[2], ap[ks][0], ap[ks][1], ap[ks][2], ap[ks][3], b0, b1);
            mma16816(c2[3], ap[ks][0], ap[ks][1], ap[ks][2], ap[ks][3], b2, b3);
        }
        int row = rt * 16 + (lane >> 2);
        #pragma unroll
        for (int n = 0; n < 4; n++) {
            int col = h * 32 + n * 8 + (lane & 3) * 2;
            *(uint32_t*)(Qs + row * 296 + col)       = packbf2(c2[n][0], c2[n][1]);
            *(uint32_t*)(Qs + (row + 8) * 296 + col) = packbf2(c2[n][2], c2[n][3]);
        }
    }
    CPA_WAIT0();
    __syncthreads();

    // ---------- proj (+bias +residual +fused LN2) ----------
    float c[4][4];
    #pragma unroll
    for (int j = 0; j < 4; j++) { c[j][0]=0.f; c[j][1]=0.f; c[j][2]=0.f; c[j][3]=0.f; }
    wgemm_16x32<296, 104>(c, q_base, w_base, lane, rt * 16, cw * 32);

    int r1 = rt * 16 + (lane >> 2), r2 = r1 + 8;
    bool va = r1 < NT, vb2 = r2 < NT;
    size_t nt1 = 0, nt2 = 0;
    {
        int tl = va ? r1 : 0;
        int r = wi * 7 + tl / 7, cl = wj * 7 + tl % 7;
        int sr = r + 3;  if (sr >= Hh) sr -= Hh;
        int sc = cl + 3; if (sc >= Ww) sc -= Ww;
        nt1 = ((size_t)(bI * Hh + sr)) * Ww + sc;
        tl = vb2 ? r2 : 0;
        r = wi * 7 + tl / 7; cl = wj * 7 + tl % 7;
        sr = r + 3;  if (sr >= Hh) sr -= Hh;
        sc = cl + 3; if (sc >= Ww) sc -= Ww;
        nt2 = ((size_t)(bI * Hh + sr)) * Ww + sc;
    }
    float s1a = 0.f, s2a = 0.f, s1b = 0.f, s2b = 0.f;
    #pragma unroll
    for (int j = 0; j < 4; j++) {
        int col = cw * 32 + j * 8 + (lane & 3) * 2;
        float bi0 = __ldg(proj_b + col), bi1 = __ldg(proj_b + col + 1);
        float2 xa = va  ? *(const float2*)(x + nt1 * 96 + col) : make_float2(0.f, 0.f);
        float2 xb = vb2 ? *(const float2*)(x + nt2 * 96 + col) : make_float2(0.f, 0.f);
        float o0 = c[j][0] + bi0 + xa.x, o1 = c[j][1] + bi1 + xa.y;
        float o2 = c[j][2] + bi0 + xb.x, o3 = c[j][3] + bi1 + xb.y;
        c[j][0] = o0; c[j][1] = o1; c[j][2] = o2; c[j][3] = o3;
        if (va)  *(float2*)(g_x1 + nt1 * 96 + col) = make_float2(o0, o1);
        if (vb2) *(float2*)(g_x1 + nt2 * 96 + col) = make_float2(o2, o3);
        s1a += o0 + o1; s2a += o0 * o0 + o1 * o1;
        s1b += o2 + o3; s2b += o2 * o2 + o3 * o3;
    }
    s1a += __shfl_xor_sync(~0u, s1a, 1); s1a += __shfl_xor_sync(~0u, s1a, 2);
    s2a += __shfl_xor_sync(~0u, s2a, 1); s2a += __shfl_xor_sync(~0u, s2a, 2);
    s1b += __shfl_xor_sync(~0u, s1b, 1); s1b += __shfl_xor_sync(~0u, s1b, 2);
    s2b += __shfl_xor_sync(~0u, s2b, 1); s2b += __shfl_xor_sync(~0u, s2b, 2);
    float* red = (float*)As;
    if ((lane & 3) == 0) {
        red[r1 * 4 + cw] = s1a; red[256 + r1 * 4 + cw] = s2a;
        red[r2 * 4 + cw] = s1b; red[256 + r2 * 4 + cw] = s2b;
    }
    __syncthreads();
    float mu1 = (red[r1 * 4] + red[r1 * 4 + 1] + red[r1 * 4 + 2]) * (1.f / 96.f);
    float mu2 = (red[r2 * 4] + red[r2 * 4 + 1] + red[r2 * 4 + 2]) * (1.f / 96.f);
    float rs1 = rsqrtf((red[256 + r1 * 4] + red[256 + r1 * 4 + 1] + red[256 + r1 * 4 + 2]) * (1.f / 96.f) - mu1 * mu1 + LN_EPS);
    float rs2 = rsqrtf((red[256 + r2 * 4] + red[256 + r2 * 4 + 1] + red[256 + r2 * 4 + 2]) * (1.f / 96.f) - mu2 * mu2 + LN_EPS);
    #pragma unroll
    for (int j = 0; j < 4; j++) {
        int col = cw * 32 + j * 8 + (lane & 3) * 2;
        float gg0 = __ldg(n2g + col), gg1 = __ldg(n2g + col + 1);
        float nb0 = __ldg(n2b + col), nb1 = __ldg(n2b + col + 1);
        if (va)
            *(uint32_t*)(g_x2 + nt1 * 96 + col) =
                packbf2((c[j][0] - mu1) * rs1 * gg0 + nb0, (c[j][1] - mu1) * rs1 * gg1 + nb1);
        if (vb2)
            *(uint32_t*)(g_x2 + nt2 * 96 + col) =
                packbf2((c[j][2] - mu2) * rs2 * gg0 + nb0, (c[j][3] - mu2) * rs2 * gg1 + nb1);
    }
}

// =====================================================================
// MLP merged: 64-row tile, 384 threads (4x3 warp grid), H in smem,
// cp.async double-buffered weight staging (unchanged from R15)
// =====================================================================
__global__ __launch_bounds__(384, 2) void mlp_kernel(
    const float* __restrict__ fc1_b, const float* __restrict__ fc2_b,
    float* __restrict__ out)
{
    extern __shared__ char smraw[];
    __nv_bfloat16* As = (__nv_bfloat16*)smraw;               // 64*104
    __nv_bfloat16* Hs = (__nv_bfloat16*)(smraw + 13312);     // 64*392
    const int tid = threadIdx.x, lane = tid & 31, wid = tid >> 5;
    const int rt = wid & 3, cw = wid >> 2;
    const uint32_t a_base = smem_u32(As), h_base = smem_u32(Hs);
    uint32_t bbase[2] = { smem_u32(smraw + 63488), smem_u32(smraw + 83456) };

    // stage A tile + fc1 chunk0 via cp.async
    {
        const __nv_bfloat16* a0 = g_x2 + (size_t)blockIdx.x * 64 * 96;
        for (int i = tid; i < 64 * 12; i += 384) {
            int r = i / 12, c8 = i % 12;
            cpa16(a_base + (uint32_t)(r * 104 + c8 * 8) * 2, a0 + (size_t)r * 96 + c8 * 8);
        }
        const uint4* src = (const uint4*)g_w1;
        for (int i = tid; i < 1248; i += 384) cpa16(bbase[0] + i * 16, src + i);
        CPA_COMMIT();
    }
    CPA_WAIT0();
    __syncthreads();

    // ---------- fc1 + GELU -> Hs, cp.async-pipelined weight staging ----------
    for (int ch = 0; ch < 4; ch++) {
        {
            const uint4* src = (ch < 3) ? (const uint4*)(g_w1 + (ch + 1) * 96 * 104)
                                        : (const uint4*)(g_w2[0]);
            uint32_t d = bbase[(ch + 1) & 1];
            for (int i = tid; i < 1248; i += 384) cpa16(d + i * 16, src + i);
            CPA_COMMIT();
        }
        float c[4][4];
        #pragma unroll
        for (int j = 0; j < 4; j++) { c[j][0]=0.f; c[j][1]=0.f; c[j][2]=0.f; c[j][3]=0.f; }
        wgemm_16x32<104, 104>(c, a_base, bbase[ch & 1], lane, rt * 16, cw * 32);
        int row0 = rt * 16 + (lane >> 2);
        #pragma unroll
        for (int j = 0; j < 4; j++) {
            int col = ch * 96 + cw * 32 + j * 8 + (lane & 3) * 2;
            float bi0 = __ldg(fc1_b + col), bi1 = __ldg(fc1_b + col + 1);
            float v0 = c[j][0] + bi0, v1 = c[j][1] + bi1;
            float v2 = c[j][2] + bi0, v3 = c[j][3] + bi1;
            v0 = 0.5f * v0 * (1.0f + erff(v0 * 0.70710678118654752f));
            v1 = 0.5f * v1 * (1.0f + erff(v1 * 0.70710678118654752f));
            v2 = 0.5f * v2 * (1.0f + erff(v2 * 0.70710678118654752f));
            v3 = 0.5f * v3 * (1.0f + erff(v3 * 0.70710678118654752f));
            *(uint32_t*)(Hs + row0 * 392 + col)       = packbf2(v0, v1);
            *(uint32_t*)(Hs + (row0 + 8) * 392 + col) = packbf2(v2, v3);
        }
        CPA_WAIT0();
        __syncthreads();
    }

    // ---------- fc2: accumulate over 4 K-chunks from Hs ----------
    float c2[4][4];
    #pragma unroll
    for (int j = 0; j < 4; j++) { c2[j][0]=0.f; c2[j][1]=0.f; c2[j][2]=0.f; c2[j][3]=0.f; }
    for (int kc = 0; kc < 4; kc++) {
        if (kc < 3) {
            const uint4* src = (const uint4*)(g_w2[kc + 1]);
            uint32_t d = bbase[(kc + 1) & 1];
            for (int i = tid; i < 1248; i += 384) cpa16(d + i * 16, src + i);
            CPA_COMMIT();
        }
        wgemm_16x32<392, 104>(c2, h_base + kc * 192, bbase[kc & 1], lane, rt * 16, cw * 32);
        if (kc < 3) { CPA_WAIT0(); __syncthreads(); }
    }

    // ---------- bias + residual -> out ----------
    const size_t row0 = (size_t)blockIdx.x * 64 + rt * 16 + (lane >> 2);
    #pragma unroll
    for (int j = 0; j < 4; j++) {
        int col = cw * 32 + j * 8 + (lane & 3) * 2;
        float bi0 = __ldg(fc2_b + col), bi1 = __ldg(fc2_b + col + 1);
        float2 r0 = *(const float2*)(g_x1 + row0 * 96 + col);
        float2 r1 = *(const float2*)(g_x1 + (row0 + 8) * 96 + col);
        *(float2*)(out + row0 * 96 + col)       = make_float2(c2[j][0] + bi0 + r0.x, c2[j][1] + bi1 + r0.y);
        *(float2*)(out + (row0 + 8) * 96 + col) = make_float2(c2[j][2] + bi0 + r1.x, c2[j][3] + bi1 + r1.y);
    }
}

// =====================================================================
extern "C" void kernel_launch(void* const* d_in, const int* in_sizes, int n_in,
                              void* d_out, int out_size)
{
    (void)in_sizes; (void)n_in; (void)out_size;
    const float* x      = (const float*)d_in[0];
    const float* n1g    = (const float*)d_in[2];
    const float* n1b    = (const float*)d_in[3];
    const float* qkv_w  = (const float*)d_in[4];
    const float* qkv_b  = (const float*)d_in[5];
    const float* proj_w = (const float*)d_in[6];
    const float* proj_b = (const float*)d_in[7];
    const float* n2g    = (const float*)d_in[8];
    const float* n2b    = (const float*)d_in[9];
    const float* fc1_w  = (const float*)d_in[10];
    const float* fc1_b  = (const float*)d_in[11];
    const float* fc2_w  = (const float*)d_in[12];
    const float* fc2_b  = (const float*)d_in[13];
    float* out = (float*)d_out;

    const int smAttn = 111168;
    const int smMlp  = 103424;

    cudaFuncSetAttribute(attn_kernel, cudaFuncAttributeMaxDynamicSharedMemorySize, smAttn);
    cudaFuncSetAttribute(mlp_kernel,  cudaFuncAttributeMaxDynamicSharedMemorySize, smMlp);

    prep_weights<<<432, 256>>>(qkv_w, proj_w, fc1_w, fc2_w);
    attn_kernel<<<8192, 384, smAttn>>>(x, n1g, n1b, qkv_b, proj_b, n2g, n2b);
    mlp_kernel<<<NTOKENS/64, 384, smMlp>>>(fc1_b, fc2_b, out);
}